// round 8
// baseline (speedup 1.0000x reference)
#include <cuda_runtime.h>
#include <cuda_bf16.h>
#include <mma.h>

using namespace nvcuda;

#define BATCH 64
#define SEQ   512
#define HID   512
#define GATES 2048
#define KIN   96
#define ODIM  128

#define NB_SCAN 128     // 64 layer-0 CTAs + 64 layer-1 CTAs
#define NT_SCAN 512
#define NGRP    16      // barrier groups of 8 CTAs
#define CCOLS   32
#define APAD    516     // mod 32 = 4, float4-aligned, 2064B mult of 16
#define W1PAD   1028
#define SGP     36      // 144B, mult of 16 for wmma store
// layer-0: As[64][APAD] + Ws[32][APAD];   sg aliases As: [4][64][SGP]
#define L0_A_FLOATS (64 * APAD)
#define L0_TOTAL    ((64 + CCOLS) * APAD)          // 49536
// layer-1: Ws1[32][W1PAD] + As1[32][APAD]; sg aliases As1: [8][32][SGP]
#define L1_W_FLOATS (CCOLS * W1PAD)                // 32896
#define L1_TOTAL    (L1_W_FLOATS + 32 * APAD)      // 49408
#define SCAN_SMEM_BYTES (L0_TOTAL * 4)             // 198,144 B

// ---------------- static device scratch ----------------
__device__ float g_xproj[(size_t)BATCH * SEQ * GATES];
__device__ float g_xcat[(size_t)BATCH * SEQ * KIN];
__device__ float g_Wih0p[GATES * KIN];
__device__ float g_Whh0p[GATES * HID];
__device__ float g_Wih1p[GATES * HID];
__device__ float g_Whh1p[GATES * HID];
__device__ float g_biasP[2][GATES];
__device__ float g_hbuf0[2][BATCH * HID];
__device__ float g_hbuf1[2][BATCH * HID];
__device__ unsigned g_grp[NGRP][32];   // per-group arrival counters, 128B apart
__device__ unsigned g_root;            // group-completion counter
__device__ unsigned g_epoch;           // completed-round counter

// ---------------- sync primitives ----------------
__device__ __forceinline__ unsigned ld_acquire_gpu(unsigned* p) {
    unsigned v;
    asm volatile("ld.acquire.gpu.global.u32 %0, [%1];" : "=r"(v) : "l"(p) : "memory");
    return v;
}
__device__ __forceinline__ unsigned atom_add_acqrel_gpu(unsigned* p, unsigned v) {
    unsigned old;
    asm volatile("atom.acq_rel.gpu.global.add.u32 %0, [%1], %2;"
                 : "=r"(old) : "l"(p), "r"(v) : "memory");
    return old;
}
__device__ __forceinline__ void st_release_gpu(unsigned* p, unsigned v) {
    asm volatile("st.release.gpu.global.u32 [%0], %1;" :: "l"(p), "r"(v) : "memory");
}

// hierarchical monotonic-epoch grid barrier (16 groups x 8 CTAs)
__device__ __forceinline__ void grid_barrier_round(unsigned round) {
    __syncthreads();
    if (threadIdx.x == 0) {
        unsigned g = blockIdx.x >> 3;
        unsigned v = atom_add_acqrel_gpu(&g_grp[g][0], 1u);
        if (v + 1u == round * 8u) {
            unsigned r = atom_add_acqrel_gpu(&g_root, 1u);
            if (r + 1u == round * NGRP) st_release_gpu(&g_epoch, round);
        }
        while ((int)(ld_acquire_gpu(&g_epoch) - round) < 0) { }
    }
    __syncthreads();
}

__device__ __forceinline__ float sigm(float x) { return 1.0f / (1.0f + expf(-x)); }

__device__ __forceinline__ float tf32_rna(float x) {
    unsigned u;
    asm("cvt.rna.tf32.f32 %0, %1;" : "=r"(u) : "f"(x));
    return __uint_as_float(u);
}

// ---------------- prep: concat input, permute + tf32-round weights ----------------
__global__ void prep_kernel(const float* __restrict__ prim, const float* __restrict__ aux,
                            const float* __restrict__ Wih0, const float* __restrict__ Whh0,
                            const float* __restrict__ bih0, const float* __restrict__ bhh0,
                            const float* __restrict__ Wih1, const float* __restrict__ Whh1,
                            const float* __restrict__ bih1, const float* __restrict__ bhh1)
{
    size_t tid = (size_t)blockIdx.x * blockDim.x + threadIdx.x;
    size_t nth = (size_t)gridDim.x * blockDim.x;

    for (size_t i = tid; i < (size_t)BATCH * SEQ * KIN; i += nth) {
        int k = (int)(i % KIN);
        size_t bt = i / KIN;
        int b = (int)(bt / SEQ);
        g_xcat[i] = tf32_rna((k < 64) ? prim[bt * 64 + k] : aux[b * 32 + (k - 64)]);
    }
    for (size_t i = tid; i < (size_t)GATES * HID; i += nth) {
        int k  = (int)(i % HID);
        int cp = (int)(i / HID);
        int u = cp >> 2, gi = cp & 3;
        size_t r = (size_t)(gi * HID + u) * HID + k;
        g_Whh0p[i] = tf32_rna(Whh0[r]);
        g_Whh1p[i] = tf32_rna(Whh1[r]);
        g_Wih1p[i] = tf32_rna(Wih1[r]);
    }
    for (size_t i = tid; i < (size_t)GATES * KIN; i += nth) {
        int k  = (int)(i % KIN);
        int cp = (int)(i / KIN);
        int u = cp >> 2, gi = cp & 3;
        g_Wih0p[i] = tf32_rna(Wih0[(size_t)(gi * HID + u) * KIN + k]);
    }
    for (size_t i = tid; i < GATES; i += nth) {
        int u = (int)(i >> 2), gi = (int)(i & 3);
        int r = gi * HID + u;
        g_biasP[0][i] = bih0[r] + bhh0[r];
        g_biasP[1][i] = bih1[r] + bhh1[r];
    }
}

// ---------------- x_proj0 GEMM (tf32 wmma) ----------------
#define GT_M 128
#define GT_N 128
#define KCHUNK 16
#define SPAD 20

__global__ void __launch_bounds__(256) gemm_tf32()
{
    __shared__ float As[GT_M * SPAD];
    __shared__ float Bs[GT_N * SPAD];

    const float* A  = g_xcat;
    const float* Bm = g_Wih0p;
    const int K     = KIN;

    int tn = blockIdx.x;
    int tm = blockIdx.y;
    int tid = threadIdx.x;
    int wid = tid >> 5;
    int wm = wid >> 2, wn = wid & 3;

    wmma::fragment<wmma::accumulator, 16, 16, 8, float> acc[4][2];
#pragma unroll
    for (int i = 0; i < 4; i++)
#pragma unroll
        for (int j = 0; j < 2; j++) wmma::fill_fragment(acc[i][j], 0.0f);

    const float* Abase = A  + (size_t)tm * GT_M * K;
    const float* Bbase = Bm + (size_t)tn * GT_N * K;

    for (int k0 = 0; k0 < K; k0 += KCHUNK) {
        __syncthreads();
#pragma unroll
        for (int s = tid; s < GT_M * 4; s += 256) {
            int m = s >> 2, q = s & 3;
            *(float4*)&As[m * SPAD + q * 4] = *(const float4*)&Abase[(size_t)m * K + k0 + q * 4];
            *(float4*)&Bs[m * SPAD + q * 4] = *(const float4*)&Bbase[(size_t)m * K + k0 + q * 4];
        }
        __syncthreads();
#pragma unroll
        for (int ks = 0; ks < 2; ks++) {
            wmma::fragment<wmma::matrix_b, 16, 16, 8, wmma::precision::tf32, wmma::col_major> bf[2];
#pragma unroll
            for (int j = 0; j < 2; j++)
                wmma::load_matrix_sync(bf[j], &Bs[(wn * 32 + j * 16) * SPAD + ks * 8], SPAD);
#pragma unroll
            for (int i = 0; i < 4; i++) {
                wmma::fragment<wmma::matrix_a, 16, 16, 8, wmma::precision::tf32, wmma::row_major> af;
                wmma::load_matrix_sync(af, &As[(wm * 64 + i * 16) * SPAD + ks * 8], SPAD);
#pragma unroll
                for (int j = 0; j < 2; j++) wmma::mma_sync(acc[i][j], af, bf[j], acc[i][j]);
            }
        }
    }
#pragma unroll
    for (int i = 0; i < 4; i++)
#pragma unroll
        for (int j = 0; j < 2; j++) {
            int gm = tm * GT_M + wm * 64 + i * 16;
            int gn = tn * GT_N + wn * 32 + j * 16;
            wmma::store_matrix_sync(&g_xproj[(size_t)gm * GATES + gn], acc[i][j], GATES,
                                    wmma::mem_row_major);
        }
}

// ---------------- fused dual-layer persistent scan, 512 threads ----------------
__global__ void __launch_bounds__(NT_SCAN, 1) scan_fused()
{
    extern __shared__ float smem[];

    const int tid  = threadIdx.x;
    const int w    = tid >> 5;
    const int lane = tid & 31;
    const int grp  = blockIdx.x >> 6;          // 0 = layer0, 1 = layer1
    const int c    = blockIdx.x & 63;          // gate-col block [32c, 32c+32)

    // zero initial states
    for (int i = blockIdx.x * NT_SCAN + tid; i < BATCH * HID; i += NB_SCAN * NT_SCAN) {
        g_hbuf0[0][i] = 0.0f;
        g_hbuf1[0][i] = 0.0f;
    }

    unsigned round = ld_acquire_gpu(&g_epoch);   // stable at kernel start

    if (grp == 0) {
        // ---------------- layer 0 ----------------
        float* As = smem;                        // [64][APAD]
        float* Ws = smem + L0_A_FLOATS;          // [32][APAD]
        float* sg = smem;                        // alias: [4][64][SGP]

        const int mq = w & 3;                    // 16-row quarter
        const int kq = w >> 2;                   // 128-col k quarter

        {   // stage W slice once
            const float* Wg = g_Whh0p + (size_t)c * CCOLS * HID;
#pragma unroll 4
            for (int idx = tid; idx < CCOLS * 128; idx += NT_SCAN) {
                int n = idx >> 7, q = idx & 127;
                *(float4*)&Ws[n * APAD + q * 4] = *(const float4*)&Wg[(size_t)n * HID + q * 4];
            }
        }

        const int b0 = tid >> 3, ul0 = tid & 7, gc0 = ul0 * 4;   // one output/thread
        const float4 bias0 = *(const float4*)(g_biasP[0] + c * CCOLS + gc0);
        const float* xpp0 = g_xproj + (size_t)b0 * SEQ * GATES + c * CCOLS + gc0;
        const int u0 = c * 8 + ul0;
        float cst0 = 0.0f;

        grid_barrier_round(++round);             // zero-init visible

        float4 xp0 = __ldcs((const float4*)xpp0);

        for (int r = 0; r < SEQ + 1; r++) {
            if (r < SEQ) {
                const int t = r;
                const float* hread  = g_hbuf0[t & 1];
                float*       hwrite = g_hbuf0[(t & 1) ^ 1];

                // warp-local stage: rows mq*16..+16, cols kq*128..+128
                {
                    const float* src = hread + (size_t)(mq * 16) * HID + kq * 128;
                    float* dst = &As[(mq * 16) * APAD + kq * 128];
#pragma unroll
                    for (int i = 0; i < 16; i++) {
                        int idx = lane + 32 * i;
                        int row = idx >> 5, c4 = idx & 31;
                        *(float4*)(dst + row * APAD + c4 * 4) =
                            __ldcg((const float4*)(src + (size_t)row * HID + c4 * 4));
                    }
                }
                __syncthreads();

                wmma::fragment<wmma::accumulator, 16, 16, 8, float> acc[2];
                wmma::fill_fragment(acc[0], 0.0f);
                wmma::fill_fragment(acc[1], 0.0f);
                const float* Abase = &As[(mq * 16) * APAD + kq * 128];
                const float* Bbase = &Ws[kq * 128];
#pragma unroll
                for (int ks = 0; ks < 16; ks++) {
                    wmma::fragment<wmma::matrix_a, 16, 16, 8, wmma::precision::tf32, wmma::row_major> af;
                    wmma::fragment<wmma::matrix_b, 16, 16, 8, wmma::precision::tf32, wmma::col_major> bf[2];
                    wmma::load_matrix_sync(af, Abase + ks * 8, APAD);
#pragma unroll
                    for (int j = 0; j < 2; j++)
                        wmma::load_matrix_sync(bf[j], Bbase + j * 16 * APAD + ks * 8, APAD);
#pragma unroll
                    for (int j = 0; j < 2; j++) wmma::mma_sync(acc[j], af, bf[j], acc[j]);
                }
                __syncthreads();
#pragma unroll
                for (int j = 0; j < 2; j++)
                    wmma::store_matrix_sync(&sg[kq * (64 * SGP) + (mq * 16) * SGP + j * 16],
                                            acc[j], SGP, wmma::mem_row_major);
                __syncthreads();

                {
                    float4 s0 = *(const float4*)&sg[0 * (64 * SGP) + b0 * SGP + gc0];
                    float4 s1 = *(const float4*)&sg[1 * (64 * SGP) + b0 * SGP + gc0];
                    float4 s2 = *(const float4*)&sg[2 * (64 * SGP) + b0 * SGP + gc0];
                    float4 s3 = *(const float4*)&sg[3 * (64 * SGP) + b0 * SGP + gc0];
                    float pi = s0.x + s1.x + s2.x + s3.x + xp0.x + bias0.x;
                    float pf = s0.y + s1.y + s2.y + s3.y + xp0.y + bias0.y;
                    float pg = s0.z + s1.z + s2.z + s3.z + xp0.z + bias0.z;
                    float po = s0.w + s1.w + s2.w + s3.w + xp0.w + bias0.w;
                    float ig = sigm(pi), fg = sigm(pf), gg = tanhf(pg), og = sigm(po);
                    cst0 = fg * cst0 + ig * gg;
                    hwrite[b0 * HID + u0] = og * tanhf(cst0);
                }
                int tn = (t + 1 < SEQ) ? (t + 1) : (SEQ - 1);
                xp0 = __ldcs((const float4*)(xpp0 + (size_t)tn * GATES));
            }
            grid_barrier_round(++round);
        }
    } else {
        // ---------------- layer 1 (lag 1) ----------------
        float* Ws1 = smem;                       // [32][W1PAD]: cols 0-511 Wih1, 512-1023 Whh1
        float* As1 = smem + L1_W_FLOATS;         // [32][APAD]
        float* sg  = As1;                        // alias: [8][32][SGP]

        const int mq = w & 1;                    // 16-row half within the 32-row m-half
        const int kq = w >> 1;                   // 64-col k chunk (0-7)

        {   // stage concat W once: 32 rows x 1024
            const float* Wx = g_Wih1p + (size_t)c * CCOLS * HID;
            const float* Wh = g_Whh1p + (size_t)c * CCOLS * HID;
#pragma unroll 4
            for (int idx = tid; idx < CCOLS * 256; idx += NT_SCAN) {
                int n = idx >> 8, q = idx & 255;
                const float* src = (q < 128) ? (Wx + (size_t)n * HID + q * 4)
                                             : (Wh + (size_t)n * HID + (q - 128) * 4);
                *(float4*)&Ws1[n * W1PAD + q * 4] = *(const float4*)src;
            }
        }

        const int bl = tid >> 3, ul = tid & 7, gc = ul * 4;   // threads 0-255: one (b,u)/m-half
        const float4 biasq = *(const float4*)(g_biasP[1] + c * CCOLS + gc);
        const int u = c * 8 + ul;
        float cstA = 0.0f, cstB = 0.0f;

        grid_barrier_round(++round);

        // per-lane staging coords for a 16x64 tile: 8 float4s
        // idx = lane + 32*i : row = idx>>4 (0..15), c4 = idx&15 (0..15)
        float4 pfA[8], pfB[8];

#define L1_LOAD(dstreg, srcbuf, rb_)                                                   \
        {                                                                              \
            const float* s_ = (srcbuf) + (size_t)((rb_) + mq * 16) * HID + kq * 64;    \
            _Pragma("unroll")                                                          \
            for (int i = 0; i < 8; i++) {                                              \
                int idx = lane + 32 * i;                                               \
                int row = idx >> 4, c4 = idx & 15;                                     \
                dstreg[i] = __ldcg((const float4*)(s_ + (size_t)row * HID + c4 * 4));  \
            }                                                                          \
        }
#define L1_STORE(srcreg)                                                               \
        {                                                                              \
            float* d_ = &As1[(mq * 16) * APAD + kq * 64];                              \
            _Pragma("unroll")                                                          \
            for (int i = 0; i < 8; i++) {                                              \
                int idx = lane + 32 * i;                                               \
                int row = idx >> 4, c4 = idx & 15;                                     \
                *(float4*)(d_ + row * APAD + c4 * 4) = srcreg[i];                      \
            }                                                                          \
        }
#define L1_MMA(accv, pass_)                                                            \
        {                                                                              \
            const float* Ab_ = &As1[(mq * 16) * APAD + kq * 64];                       \
            const float* Bb_ = &Ws1[(pass_) * 512 + kq * 64];                          \
            _Pragma("unroll")                                                          \
            for (int ks = 0; ks < 8; ks++) {                                           \
                wmma::fragment<wmma::matrix_a, 16, 16, 8, wmma::precision::tf32,       \
                               wmma::row_major> af;                                    \
                wmma::fragment<wmma::matrix_b, 16, 16, 8, wmma::precision::tf32,       \
                               wmma::col_major> bf[2];                                 \
                wmma::load_matrix_sync(af, Ab_ + ks * 8, APAD);                        \
                _Pragma("unroll")                                                      \
                for (int j = 0; j < 2; j++)                                            \
                    wmma::load_matrix_sync(bf[j], Bb_ + j * 16 * W1PAD + ks * 8,       \
                                           W1PAD);                                     \
                _Pragma("unroll")                                                      \
                for (int j = 0; j < 2; j++) wmma::mma_sync(accv[j], af, bf[j], accv[j]);\
            }                                                                          \
        }

        for (int r = 0; r < SEQ + 1; r++) {
            if (r >= 1) {
                const int t = r - 1;
                const float* h0read = g_hbuf0[(t & 1) ^ 1];   // h0[t]
                const float* h1read = g_hbuf1[t & 1];         // h1[t-1]
                float*       hwrite = g_hbuf1[(t & 1) ^ 1];

                wmma::fragment<wmma::accumulator, 16, 16, 8, float> acc[2];

                // ---- m-half 0 ----
                wmma::fill_fragment(acc[0], 0.0f);
                wmma::fill_fragment(acc[1], 0.0f);
                L1_LOAD(pfA, h0read, 0);
                L1_STORE(pfA);  L1_LOAD(pfB, h1read, 0);
                __syncthreads();
                L1_MMA(acc, 0);
                __syncthreads();
                L1_STORE(pfB);  L1_LOAD(pfA, h0read, 32);     // prefetch mh1 pass0
                __syncthreads();
                L1_MMA(acc, 1);
                __syncthreads();
#pragma unroll
                for (int j = 0; j < 2; j++)
                    wmma::store_matrix_sync(&sg[kq * (32 * SGP) + (mq * 16) * SGP + j * 16],
                                            acc[j], SGP, wmma::mem_row_major);
                __syncthreads();
                if (tid < 256) {
                    float pi = biasq.x, pf = biasq.y, pg = biasq.z, po = biasq.w;
#pragma unroll
                    for (int q = 0; q < 8; q++) {
                        float4 s = *(const float4*)&sg[q * (32 * SGP) + bl * SGP + gc];
                        pi += s.x; pf += s.y; pg += s.z; po += s.w;
                    }
                    float ig = sigm(pi), fg = sigm(pf), gg = tanhf(pg), og = sigm(po);
                    cstA = fg * cstA + ig * gg;
                    hwrite[bl * HID + u] = og * tanhf(cstA);
                }
                L1_LOAD(pfB, h1read, 32);                     // prefetch mh1 pass1
                __syncthreads();                              // sg readers done

                // ---- m-half 1 ----
                wmma::fill_fragment(acc[0], 0.0f);
                wmma::fill_fragment(acc[1], 0.0f);
                L1_STORE(pfA);
                __syncthreads();
                L1_MMA(acc, 0);
                __syncthreads();
                L1_STORE(pfB);
                __syncthreads();
                L1_MMA(acc, 1);
                __syncthreads();
#pragma unroll
                for (int j = 0; j < 2; j++)
                    wmma::store_matrix_sync(&sg[kq * (32 * SGP) + (mq * 16) * SGP + j * 16],
                                            acc[j], SGP, wmma::mem_row_major);
                __syncthreads();
                if (tid < 256) {
                    float pi = biasq.x, pf = biasq.y, pg = biasq.z, po = biasq.w;
#pragma unroll
                    for (int q = 0; q < 8; q++) {
                        float4 s = *(const float4*)&sg[q * (32 * SGP) + bl * SGP + gc];
                        pi += s.x; pf += s.y; pg += s.z; po += s.w;
                    }
                    float ig = sigm(pi), fg = sigm(pf), gg = tanhf(pg), og = sigm(po);
                    cstB = fg * cstB + ig * gg;
                    hwrite[(32 + bl) * HID + u] = og * tanhf(cstB);
                }
            }
            grid_barrier_round(++round);
        }
    }
}

// ---------------- output projection (vectorized) ----------------
__global__ void out_kernel(const float* __restrict__ Wout, const float* __restrict__ bout,
                           float* __restrict__ out)
{
    int b = blockIdx.x;
    int o = threadIdx.x;
    const float4* h4 = (const float4*)(g_hbuf1[0] + b * HID);   // final h1 in buffer 0
    const float4* w4 = (const float4*)(Wout + (size_t)o * HID);
    float acc = 0.0f;
#pragma unroll 16
    for (int i = 0; i < HID / 4; i++) {
        float4 hh = h4[i], ww = w4[i];
        acc += hh.x * ww.x + hh.y * ww.y + hh.z * ww.z + hh.w * ww.w;
    }
    out[b * ODIM + o] = acc + bout[o];
}

// ---------------- launch ----------------
extern "C" void kernel_launch(void* const* d_in, const int* in_sizes, int n_in,
                              void* d_out, int out_size)
{
    (void)in_sizes; (void)n_in; (void)out_size;
    const float* prim = (const float*)d_in[0];
    const float* aux  = (const float*)d_in[1];
    const float* Wih0 = (const float*)d_in[2];
    const float* Whh0 = (const float*)d_in[3];
    const float* bih0 = (const float*)d_in[4];
    const float* bhh0 = (const float*)d_in[5];
    const float* Wih1 = (const float*)d_in[6];
    const float* Whh1 = (const float*)d_in[7];
    const float* bih1 = (const float*)d_in[8];
    const float* bhh1 = (const float*)d_in[9];
    const float* Wout = (const float*)d_in[10];
    const float* bout = (const float*)d_in[11];
    float* out = (float*)d_out;

    static bool attr_set = false;
    if (!attr_set) {
        cudaFuncSetAttribute(scan_fused, cudaFuncAttributeMaxDynamicSharedMemorySize,
                             SCAN_SMEM_BYTES);
        attr_set = true;
    }

    prep_kernel<<<1024, 256>>>(prim, aux, Wih0, Whh0, bih0, bhh0, Wih1, Whh1, bih1, bhh1);
    gemm_tf32<<<dim3(16, 256), 256>>>();                      // x_proj0
    scan_fused<<<NB_SCAN, NT_SCAN, SCAN_SMEM_BYTES>>>();      // both layers, pipelined
    out_kernel<<<BATCH, ODIM>>>(Wout, bout, out);
}

// round 9
// speedup vs baseline: 1.1602x; 1.1602x over previous
#include <cuda_runtime.h>
#include <cuda_bf16.h>
#include <mma.h>

using namespace nvcuda;

#define BATCH 64
#define SEQ   512
#define HID   512
#define GATES 2048
#define KIN   96
#define ODIM  128

#define NB_SCAN 128     // 64 layer-0 CTAs + 64 layer-1 CTAs
#define NT_SCAN 256
#define CCOLS   32
#define APAD    516
#define W1PAD   1028
#define SGP     36
#define L0_A_FLOATS (64 * APAD)
#define L0_TOTAL    ((64 + CCOLS) * APAD)          // 49536
#define L1_W_FLOATS (CCOLS * W1PAD)                // 32896
#define L1_TOTAL    (L1_W_FLOATS + 32 * APAD)      // 49408
#define SCAN_SMEM_BYTES (L0_TOTAL * 4)             // 198,144 B

// ---------------- static device scratch ----------------
__device__ float g_xproj[(size_t)BATCH * SEQ * GATES];
__device__ float g_xcat[(size_t)BATCH * SEQ * KIN];
__device__ float g_Wih0p[GATES * KIN];
__device__ float g_Whh0p[GATES * HID];
__device__ float g_Wih1p[GATES * HID];
__device__ float g_Whh1p[GATES * HID];
__device__ float g_biasP[2][GATES];
__device__ float g_hbuf0[2][BATCH * HID];
__device__ float g_hbuf1[2][BATCH * HID];
__device__ unsigned g_flags[NB_SCAN][32];   // per-CTA round flags, 128B apart

// ---------------- sync primitives ----------------
__device__ __forceinline__ unsigned ld_acquire_gpu(const unsigned* p) {
    unsigned v;
    asm volatile("ld.acquire.gpu.global.u32 %0, [%1];" : "=r"(v) : "l"(p) : "memory");
    return v;
}
__device__ __forceinline__ void st_release_gpu(unsigned* p, unsigned v) {
    asm volatile("st.release.gpu.global.u32 [%0], %1;" :: "l"(p), "r"(v) : "memory");
}

// all-to-all flag barrier: arrival = 1 release store to own flag (no atomics);
// wait = warp 0 polls all 128 flags in parallel. Monotonic rounds, replay-safe.
__device__ __forceinline__ void grid_barrier_round(unsigned round) {
    __syncthreads();
    if (threadIdx.x < 32) {
        if (threadIdx.x == 0)
            st_release_gpu(&g_flags[blockIdx.x][0], round);
        const int lane = threadIdx.x;
        bool ok;
        do {
            ok = true;
#pragma unroll
            for (int i = 0; i < NB_SCAN / 32; i++) {
                unsigned f = ld_acquire_gpu(&g_flags[lane + 32 * i][0]);
                ok &= ((int)(f - round) >= 0);
            }
        } while (!__all_sync(0xffffffffu, ok));
    }
    __syncthreads();
}

__device__ __forceinline__ float sigm(float x) { return 1.0f / (1.0f + expf(-x)); }

__device__ __forceinline__ float tf32_rna(float x) {
    unsigned u;
    asm("cvt.rna.tf32.f32 %0, %1;" : "=r"(u) : "f"(x));
    return __uint_as_float(u);
}

// ---------------- prep: concat input, permute + tf32-round weights ----------------
__global__ void prep_kernel(const float* __restrict__ prim, const float* __restrict__ aux,
                            const float* __restrict__ Wih0, const float* __restrict__ Whh0,
                            const float* __restrict__ bih0, const float* __restrict__ bhh0,
                            const float* __restrict__ Wih1, const float* __restrict__ Whh1,
                            const float* __restrict__ bih1, const float* __restrict__ bhh1)
{
    size_t tid = (size_t)blockIdx.x * blockDim.x + threadIdx.x;
    size_t nth = (size_t)gridDim.x * blockDim.x;

    for (size_t i = tid; i < (size_t)BATCH * SEQ * KIN; i += nth) {
        int k = (int)(i % KIN);
        size_t bt = i / KIN;
        int b = (int)(bt / SEQ);
        g_xcat[i] = tf32_rna((k < 64) ? prim[bt * 64 + k] : aux[b * 32 + (k - 64)]);
    }
    for (size_t i = tid; i < (size_t)GATES * HID; i += nth) {
        int k  = (int)(i % HID);
        int cp = (int)(i / HID);
        int u = cp >> 2, gi = cp & 3;
        size_t r = (size_t)(gi * HID + u) * HID + k;
        g_Whh0p[i] = tf32_rna(Whh0[r]);
        g_Whh1p[i] = tf32_rna(Whh1[r]);
        g_Wih1p[i] = tf32_rna(Wih1[r]);
    }
    for (size_t i = tid; i < (size_t)GATES * KIN; i += nth) {
        int k  = (int)(i % KIN);
        int cp = (int)(i / KIN);
        int u = cp >> 2, gi = cp & 3;
        g_Wih0p[i] = tf32_rna(Wih0[(size_t)(gi * HID + u) * KIN + k]);
    }
    for (size_t i = tid; i < GATES; i += nth) {
        int u = (int)(i >> 2), gi = (int)(i & 3);
        int r = gi * HID + u;
        g_biasP[0][i] = bih0[r] + bhh0[r];
        g_biasP[1][i] = bih1[r] + bhh1[r];
    }
}

// ---------------- x_proj0 GEMM (tf32 wmma) ----------------
#define GT_M 128
#define GT_N 128
#define KCHUNK 16
#define SPAD 20

__global__ void __launch_bounds__(256) gemm_tf32()
{
    __shared__ float As[GT_M * SPAD];
    __shared__ float Bs[GT_N * SPAD];

    const float* A  = g_xcat;
    const float* Bm = g_Wih0p;
    const int K     = KIN;

    int tn = blockIdx.x;
    int tm = blockIdx.y;
    int tid = threadIdx.x;
    int wid = tid >> 5;
    int wm = wid >> 2, wn = wid & 3;

    wmma::fragment<wmma::accumulator, 16, 16, 8, float> acc[4][2];
#pragma unroll
    for (int i = 0; i < 4; i++)
#pragma unroll
        for (int j = 0; j < 2; j++) wmma::fill_fragment(acc[i][j], 0.0f);

    const float* Abase = A  + (size_t)tm * GT_M * K;
    const float* Bbase = Bm + (size_t)tn * GT_N * K;

    for (int k0 = 0; k0 < K; k0 += KCHUNK) {
        __syncthreads();
#pragma unroll
        for (int s = tid; s < GT_M * 4; s += 256) {
            int m = s >> 2, q = s & 3;
            *(float4*)&As[m * SPAD + q * 4] = *(const float4*)&Abase[(size_t)m * K + k0 + q * 4];
            *(float4*)&Bs[m * SPAD + q * 4] = *(const float4*)&Bbase[(size_t)m * K + k0 + q * 4];
        }
        __syncthreads();
#pragma unroll
        for (int ks = 0; ks < 2; ks++) {
            wmma::fragment<wmma::matrix_b, 16, 16, 8, wmma::precision::tf32, wmma::col_major> bf[2];
#pragma unroll
            for (int j = 0; j < 2; j++)
                wmma::load_matrix_sync(bf[j], &Bs[(wn * 32 + j * 16) * SPAD + ks * 8], SPAD);
#pragma unroll
            for (int i = 0; i < 4; i++) {
                wmma::fragment<wmma::matrix_a, 16, 16, 8, wmma::precision::tf32, wmma::row_major> af;
                wmma::load_matrix_sync(af, &As[(wm * 64 + i * 16) * SPAD + ks * 8], SPAD);
#pragma unroll
                for (int j = 0; j < 2; j++) wmma::mma_sync(acc[i][j], af, bf[j], acc[i][j]);
            }
        }
    }
#pragma unroll
    for (int i = 0; i < 4; i++)
#pragma unroll
        for (int j = 0; j < 2; j++) {
            int gm = tm * GT_M + wm * 64 + i * 16;
            int gn = tn * GT_N + wn * 32 + j * 16;
            wmma::store_matrix_sync(&g_xproj[(size_t)gm * GATES + gn], acc[i][j], GATES,
                                    wmma::mem_row_major);
        }
}

// ---------------- fused dual-layer persistent scan (R6 structure, 256 thr) ----------------
__global__ void __launch_bounds__(NT_SCAN) scan_fused()
{
    extern __shared__ float smem[];

    const int tid  = threadIdx.x;
    const int w    = tid >> 5;
    const int lane = tid & 31;
    const int grp  = blockIdx.x >> 6;          // 0 = layer0, 1 = layer1
    const int c    = blockIdx.x & 63;          // gate-col block [32c, 32c+32)

    // zero initial states
    for (int i = blockIdx.x * NT_SCAN + tid; i < BATCH * HID; i += NB_SCAN * NT_SCAN) {
        g_hbuf0[0][i] = 0.0f;
        g_hbuf1[0][i] = 0.0f;
    }

    // base round = own flag (only this CTA writes it; all flags equal between launches)
    unsigned round = ld_acquire_gpu(&g_flags[blockIdx.x][0]);

    if (grp == 0) {
        // ---------------- layer 0 ----------------
        float* As = smem;                       // [64][APAD]
        float* Ws = smem + L0_A_FLOATS;         // [32][APAD]
        float* sg = smem;                       // alias: [4][64][SGP]

        const int mh = w & 1;                   // m half (32 rows)
        const int kq = w >> 1;                  // k quarter (128 cols)

        {   // stage W slice once
            const float* Wg = g_Whh0p + (size_t)c * CCOLS * HID;
#pragma unroll 4
            for (int idx = tid; idx < CCOLS * 128; idx += NT_SCAN) {
                int n = idx >> 7, q = idx & 127;
                *(float4*)&Ws[n * APAD + q * 4] = *(const float4*)&Wg[(size_t)n * HID + q * 4];
            }
        }

        const int b0 = tid >> 3,  ul0 = tid & 7,  gc0 = ul0 * 4;
        const int p1 = tid + NT_SCAN;
        const int b1 = p1 >> 3,   ul1 = p1 & 7,   gc1 = ul1 * 4;
        const float4 bias0 = *(const float4*)(g_biasP[0] + c * CCOLS + gc0);
        const float4 bias1 = *(const float4*)(g_biasP[0] + c * CCOLS + gc1);
        const float* xpp0 = g_xproj + (size_t)b0 * SEQ * GATES + c * CCOLS + gc0;
        const float* xpp1 = g_xproj + (size_t)b1 * SEQ * GATES + c * CCOLS + gc1;
        const int u0 = c * 8 + ul0, u1 = c * 8 + ul1;
        float cst0 = 0.0f, cst1 = 0.0f;

        grid_barrier_round(++round);            // zero-init visible

        float4 xp0 = __ldcs((const float4*)xpp0);
        float4 xp1 = __ldcs((const float4*)xpp1);

        for (int r = 0; r < SEQ + 1; r++) {
            if (r < SEQ) {
                const int t = r;
                const float* hread  = g_hbuf0[t & 1];
                float*       hwrite = g_hbuf0[(t & 1) ^ 1];

                // warp-local A staging (warp-private tile)
                {
                    const float* src = hread + (size_t)(mh * 32) * HID + kq * 128 + lane * 4;
                    float* dst = &As[(mh * 32) * APAD + kq * 128 + lane * 4];
#pragma unroll
                    for (int i = 0; i < 32; i++)
                        *(float4*)(dst + i * APAD) = __ldcg((const float4*)(src + (size_t)i * HID));
                }
                __syncwarp();

                wmma::fragment<wmma::accumulator, 16, 16, 8, float> acc[2][2];
#pragma unroll
                for (int i = 0; i < 2; i++)
#pragma unroll
                    for (int j = 0; j < 2; j++) wmma::fill_fragment(acc[i][j], 0.0f);

                const float* Abase = &As[mh * 32 * APAD + kq * 128];
                const float* Bbase = &Ws[kq * 128];
#pragma unroll
                for (int ks = 0; ks < 16; ks++) {
                    wmma::fragment<wmma::matrix_a, 16, 16, 8, wmma::precision::tf32, wmma::row_major> af[2];
                    wmma::fragment<wmma::matrix_b, 16, 16, 8, wmma::precision::tf32, wmma::col_major> bf[2];
#pragma unroll
                    for (int i = 0; i < 2; i++)
                        wmma::load_matrix_sync(af[i], Abase + i * 16 * APAD + ks * 8, APAD);
#pragma unroll
                    for (int j = 0; j < 2; j++)
                        wmma::load_matrix_sync(bf[j], Bbase + j * 16 * APAD + ks * 8, APAD);
#pragma unroll
                    for (int i = 0; i < 2; i++)
#pragma unroll
                        for (int j = 0; j < 2; j++) wmma::mma_sync(acc[i][j], af[i], bf[j], acc[i][j]);
                }
                __syncthreads();
#pragma unroll
                for (int i = 0; i < 2; i++)
#pragma unroll
                    for (int j = 0; j < 2; j++)
                        wmma::store_matrix_sync(&sg[kq * (64 * SGP) + (mh * 32 + i * 16) * SGP + j * 16],
                                                acc[i][j], SGP, wmma::mem_row_major);
                __syncthreads();

                {
                    float4 s0 = *(const float4*)&sg[0 * (64 * SGP) + b0 * SGP + gc0];
                    float4 s1 = *(const float4*)&sg[1 * (64 * SGP) + b0 * SGP + gc0];
                    float4 s2 = *(const float4*)&sg[2 * (64 * SGP) + b0 * SGP + gc0];
                    float4 s3 = *(const float4*)&sg[3 * (64 * SGP) + b0 * SGP + gc0];
                    float pi = s0.x + s1.x + s2.x + s3.x + xp0.x + bias0.x;
                    float pf = s0.y + s1.y + s2.y + s3.y + xp0.y + bias0.y;
                    float pg = s0.z + s1.z + s2.z + s3.z + xp0.z + bias0.z;
                    float po = s0.w + s1.w + s2.w + s3.w + xp0.w + bias0.w;
                    float ig = sigm(pi), fg = sigm(pf), gg = tanhf(pg), og = sigm(po);
                    cst0 = fg * cst0 + ig * gg;
                    hwrite[b0 * HID + u0] = og * tanhf(cst0);
                }
                {
                    float4 s0 = *(const float4*)&sg[0 * (64 * SGP) + b1 * SGP + gc1];
                    float4 s1 = *(const float4*)&sg[1 * (64 * SGP) + b1 * SGP + gc1];
                    float4 s2 = *(const float4*)&sg[2 * (64 * SGP) + b1 * SGP + gc1];
                    float4 s3 = *(const float4*)&sg[3 * (64 * SGP) + b1 * SGP + gc1];
                    float pi = s0.x + s1.x + s2.x + s3.x + xp1.x + bias1.x;
                    float pf = s0.y + s1.y + s2.y + s3.y + xp1.y + bias1.y;
                    float pg = s0.z + s1.z + s2.z + s3.z + xp1.z + bias1.z;
                    float po = s0.w + s1.w + s2.w + s3.w + xp1.w + bias1.w;
                    float ig = sigm(pi), fg = sigm(pf), gg = tanhf(pg), og = sigm(po);
                    cst1 = fg * cst1 + ig * gg;
                    hwrite[b1 * HID + u1] = og * tanhf(cst1);
                }
                // prefetch next xproj before the barrier
                int tn = (t + 1 < SEQ) ? (t + 1) : (SEQ - 1);
                xp0 = __ldcs((const float4*)(xpp0 + (size_t)tn * GATES));
                xp1 = __ldcs((const float4*)(xpp1 + (size_t)tn * GATES));
            }
            grid_barrier_round(++round);
        }
    } else {
        // ---------------- layer 1 (lag 1) ----------------
        float* Ws1 = smem;                      // [32][W1PAD]: cols 0-511 Wih1, 512-1023 Whh1
        float* As1 = smem + L1_W_FLOATS;        // [32][APAD]
        float* sg  = As1;                       // alias: [8][32][SGP] (uses [4] groups here)

        const int mhw = w & 1;                  // 16-row half within the 32-row block
        const int kq  = w >> 1;                 // 128-col k quarter

        {   // stage concat W once: 32 rows x 1024
            const float* Wx = g_Wih1p + (size_t)c * CCOLS * HID;
            const float* Wh = g_Whh1p + (size_t)c * CCOLS * HID;
#pragma unroll 4
            for (int idx = tid; idx < CCOLS * 256; idx += NT_SCAN) {
                int n = idx >> 8, q = idx & 255;
                const float* src = (q < 128) ? (Wx + (size_t)n * HID + q * 4)
                                             : (Wh + (size_t)n * HID + (q - 128) * 4);
                *(float4*)&Ws1[n * W1PAD + q * 4] = *(const float4*)src;
            }
        }

        const int bl = tid >> 3, ul = tid & 7, gc = ul * 4;
        const float4 biasq = *(const float4*)(g_biasP[1] + c * CCOLS + gc);
        const int u = c * 8 + ul;
        float cstA = 0.0f, cstB = 0.0f;

        grid_barrier_round(++round);

        for (int r = 0; r < SEQ + 1; r++) {
            if (r >= 1) {
                const int t = r - 1;
                const float* h0read = g_hbuf0[(t & 1) ^ 1];   // h0[t]
                const float* h1read = g_hbuf1[t & 1];         // h1[t-1]
                float*       hwrite = g_hbuf1[(t & 1) ^ 1];

#pragma unroll
                for (int mh2 = 0; mh2 < 2; mh2++) {
                    const int rb = mh2 * 32;

                    wmma::fragment<wmma::accumulator, 16, 16, 8, float> acc[2];
                    wmma::fill_fragment(acc[0], 0.0f);
                    wmma::fill_fragment(acc[1], 0.0f);

#pragma unroll
                    for (int pass = 0; pass < 2; pass++) {
                        const float* src = pass ? h1read : h0read;
                        {   // warp-private stage: rows rb+mhw*16..+16, cols kq*128..+128
                            const float* s = src + (size_t)(rb + mhw * 16) * HID + kq * 128 + lane * 4;
                            float* dst = &As1[(mhw * 16) * APAD + kq * 128 + lane * 4];
#pragma unroll
                            for (int i = 0; i < 16; i++)
                                *(float4*)(dst + i * APAD) = __ldcg((const float4*)(s + (size_t)i * HID));
                        }
                        __syncwarp();

                        const float* Abase = &As1[(mhw * 16) * APAD + kq * 128];
                        const float* Bbase = &Ws1[pass * 512 + kq * 128];
#pragma unroll
                        for (int ks = 0; ks < 16; ks++) {
                            wmma::fragment<wmma::matrix_a, 16, 16, 8, wmma::precision::tf32, wmma::row_major> af;
                            wmma::fragment<wmma::matrix_b, 16, 16, 8, wmma::precision::tf32, wmma::col_major> bf[2];
                            wmma::load_matrix_sync(af, Abase + ks * 8, APAD);
#pragma unroll
                            for (int j = 0; j < 2; j++)
                                wmma::load_matrix_sync(bf[j], Bbase + j * 16 * W1PAD + ks * 8, W1PAD);
#pragma unroll
                            for (int j = 0; j < 2; j++) wmma::mma_sync(acc[j], af, bf[j], acc[j]);
                        }
                        __syncwarp();
                    }
                    __syncthreads();   // all warps done with As1 before sg alias write
#pragma unroll
                    for (int j = 0; j < 2; j++)
                        wmma::store_matrix_sync(&sg[kq * (32 * SGP) + (mhw * 16) * SGP + j * 16],
                                                acc[j], SGP, wmma::mem_row_major);
                    __syncthreads();

                    {   // elementwise for 32 batches
                        float4 s0 = *(const float4*)&sg[0 * (32 * SGP) + bl * SGP + gc];
                        float4 s1 = *(const float4*)&sg[1 * (32 * SGP) + bl * SGP + gc];
                        float4 s2 = *(const float4*)&sg[2 * (32 * SGP) + bl * SGP + gc];
                        float4 s3 = *(const float4*)&sg[3 * (32 * SGP) + bl * SGP + gc];
                        float pi = s0.x + s1.x + s2.x + s3.x + biasq.x;
                        float pf = s0.y + s1.y + s2.y + s3.y + biasq.y;
                        float pg = s0.z + s1.z + s2.z + s3.z + biasq.z;
                        float po = s0.w + s1.w + s2.w + s3.w + biasq.w;
                        float ig = sigm(pi), fg = sigm(pf), gg = tanhf(pg), og = sigm(po);
                        float& cst = mh2 ? cstB : cstA;
                        cst = fg * cst + ig * gg;
                        hwrite[(rb + bl) * HID + u] = og * tanhf(cst);
                    }
                    __syncthreads();   // elementwise done before next m-half restages As1/sg
                }
            }
            grid_barrier_round(++round);
        }
    }
}

// ---------------- output projection (split-K x2 + smem reduce) ----------------
__global__ void out_kernel(const float* __restrict__ Wout, const float* __restrict__ bout,
                           float* __restrict__ out)
{
    __shared__ float red[256];
    int b = blockIdx.x;
    int t = threadIdx.x;          // 256
    int o = t & 127, half = t >> 7;
    const float4* h4 = (const float4*)(g_hbuf1[0] + b * HID) + half * 64;
    const float4* w4 = (const float4*)(Wout + (size_t)o * HID) + half * 64;
    float acc = 0.0f;
#pragma unroll 16
    for (int i = 0; i < 64; i++) {
        float4 hh = h4[i], ww = w4[i];
        acc += hh.x * ww.x + hh.y * ww.y + hh.z * ww.z + hh.w * ww.w;
    }
    red[t] = acc;
    __syncthreads();
    if (t < 128) out[b * ODIM + t] = red[t] + red[t + 128] + bout[t];
}

// ---------------- launch ----------------
extern "C" void kernel_launch(void* const* d_in, const int* in_sizes, int n_in,
                              void* d_out, int out_size)
{
    (void)in_sizes; (void)n_in; (void)out_size;
    const float* prim = (const float*)d_in[0];
    const float* aux  = (const float*)d_in[1];
    const float* Wih0 = (const float*)d_in[2];
    const float* Whh0 = (const float*)d_in[3];
    const float* bih0 = (const float*)d_in[4];
    const float* bhh0 = (const float*)d_in[5];
    const float* Wih1 = (const float*)d_in[6];
    const float* Whh1 = (const float*)d_in[7];
    const float* bih1 = (const float*)d_in[8];
    const float* bhh1 = (const float*)d_in[9];
    const float* Wout = (const float*)d_in[10];
    const float* bout = (const float*)d_in[11];
    float* out = (float*)d_out;

    static bool attr_set = false;
    if (!attr_set) {
        cudaFuncSetAttribute(scan_fused, cudaFuncAttributeMaxDynamicSharedMemorySize,
                             SCAN_SMEM_BYTES);
        attr_set = true;
    }

    prep_kernel<<<1024, 256>>>(prim, aux, Wih0, Whh0, bih0, bhh0, Wih1, Whh1, bih1, bhh1);
    gemm_tf32<<<dim3(16, 256), 256>>>();                      // x_proj0
    scan_fused<<<NB_SCAN, NT_SCAN, SCAN_SMEM_BYTES>>>();      // both layers, pipelined
    out_kernel<<<BATCH, 256>>>(Wout, bout, out);
}

// round 11
// speedup vs baseline: 2.8417x; 2.4493x over previous
#include <cuda_runtime.h>
#include <cuda_bf16.h>
#include <cuda_fp16.h>
#include <mma.h>

using namespace nvcuda;

#define BATCH 64
#define SEQ   512
#define HID   512
#define GATES 2048
#define KIN   96
#define ODIM  128

#define NB_SCAN 128     // 64 layer-0 CTAs + 64 layer-1 CTAs
#define NT_SCAN 256
#define CCOLS   32
#define APADH   520     // 512+8 halfs: row stride 1040B ≡ 16B mod 128B -> LDSM conflict-free
#define W1PADH  1032    // 1024+8 halfs: 2064B ≡ 16B mod 128B
#define SGP     36
// layer-0: As half[64][APADH] + Ws half[32][APADH]; sg(float) aliases As
#define L0_A_BYTES   (64 * APADH * 2)              // 66,560
#define L0_TOTAL_B   (L0_A_BYTES + 32 * APADH * 2) // 99,840
// layer-1: Ws1 half[32][W1PADH] + As1 half[32][APADH]; sg(float) aliases As1
#define L1_W_BYTES   (32 * W1PADH * 2)             // 66,048
#define SCAN_SMEM_BYTES L0_TOTAL_B                 // 99,840 (>= L1 total 99,328)

// ---------------- static device scratch ----------------
__device__ float  g_xproj[(size_t)BATCH * SEQ * GATES];
__device__ float  g_xcat[(size_t)BATCH * SEQ * KIN];
__device__ float  g_Wih0p[GATES * KIN];
__device__ __half g_Whh0h[GATES * HID];
__device__ __half g_Wih1h[GATES * HID];
__device__ __half g_Whh1h[GATES * HID];
__device__ float  g_biasP[2][GATES];
__device__ __half g_hbuf0[2][BATCH * HID];
__device__ __half g_hbuf1[2][BATCH * HID];
__device__ unsigned g_flags[NB_SCAN][32];   // per-CTA round flags, 128B apart

// ---------------- sync primitives (R8 verbatim) ----------------
__device__ __forceinline__ unsigned ld_acquire_gpu(const unsigned* p) {
    unsigned v;
    asm volatile("ld.acquire.gpu.global.u32 %0, [%1];" : "=r"(v) : "l"(p) : "memory");
    return v;
}
__device__ __forceinline__ void st_release_gpu(unsigned* p, unsigned v) {
    asm volatile("st.release.gpu.global.u32 [%0], %1;" :: "l"(p), "r"(v) : "memory");
}

// all-to-all flag barrier: arrival = 1 release store to own flag; wait = warp 0
// polls all 128 flags in parallel. Monotonic rounds, replay-safe.
__device__ __forceinline__ void grid_barrier_round(unsigned round) {
    __syncthreads();
    if (threadIdx.x < 32) {
        if (threadIdx.x == 0)
            st_release_gpu(&g_flags[blockIdx.x][0], round);
        const int lane = threadIdx.x;
        bool ok;
        do {
            ok = true;
#pragma unroll
            for (int i = 0; i < NB_SCAN / 32; i++) {
                unsigned f = ld_acquire_gpu(&g_flags[lane + 32 * i][0]);
                ok &= ((int)(f - round) >= 0);
            }
        } while (!__all_sync(0xffffffffu, ok));
    }
    __syncthreads();
}

__device__ __forceinline__ float sigm(float x) { return 1.0f / (1.0f + expf(-x)); }

__device__ __forceinline__ float tf32_rna(float x) {
    unsigned u;
    asm("cvt.rna.tf32.f32 %0, %1;" : "=r"(u) : "f"(x));
    return __uint_as_float(u);
}

// ---------------- prep: concat input; permute weights (col' = 4u+gate); fp16 scan weights ----------------
__global__ void prep_kernel(const float* __restrict__ prim, const float* __restrict__ aux,
                            const float* __restrict__ Wih0, const float* __restrict__ Whh0,
                            const float* __restrict__ bih0, const float* __restrict__ bhh0,
                            const float* __restrict__ Wih1, const float* __restrict__ Whh1,
                            const float* __restrict__ bih1, const float* __restrict__ bhh1)
{
    size_t tid = (size_t)blockIdx.x * blockDim.x + threadIdx.x;
    size_t nth = (size_t)gridDim.x * blockDim.x;

    for (size_t i = tid; i < (size_t)BATCH * SEQ * KIN; i += nth) {
        int k = (int)(i % KIN);
        size_t bt = i / KIN;
        int b = (int)(bt / SEQ);
        g_xcat[i] = tf32_rna((k < 64) ? prim[bt * 64 + k] : aux[b * 32 + (k - 64)]);
    }
    for (size_t i = tid; i < (size_t)GATES * HID; i += nth) {
        int k  = (int)(i % HID);
        int cp = (int)(i / HID);
        int u = cp >> 2, gi = cp & 3;
        size_t r = (size_t)(gi * HID + u) * HID + k;
        g_Whh0h[i] = __float2half(Whh0[r]);
        g_Whh1h[i] = __float2half(Whh1[r]);
        g_Wih1h[i] = __float2half(Wih1[r]);
    }
    for (size_t i = tid; i < (size_t)GATES * KIN; i += nth) {
        int k  = (int)(i % KIN);
        int cp = (int)(i / KIN);
        int u = cp >> 2, gi = cp & 3;
        g_Wih0p[i] = tf32_rna(Wih0[(size_t)(gi * HID + u) * KIN + k]);
    }
    for (size_t i = tid; i < GATES; i += nth) {
        int u = (int)(i >> 2), gi = (int)(i & 3);
        int r = gi * HID + u;
        g_biasP[0][i] = bih0[r] + bhh0[r];
        g_biasP[1][i] = bih1[r] + bhh1[r];
    }
}

// ---------------- x_proj0 GEMM (tf32 wmma, unchanged) ----------------
#define GT_M 128
#define GT_N 128
#define KCHUNK 16
#define SPAD 20

__global__ void __launch_bounds__(256) gemm_tf32()
{
    __shared__ float As[GT_M * SPAD];
    __shared__ float Bs[GT_N * SPAD];

    const float* A  = g_xcat;
    const float* Bm = g_Wih0p;
    const int K     = KIN;

    int tn = blockIdx.x;
    int tm = blockIdx.y;
    int tid = threadIdx.x;
    int wid = tid >> 5;
    int wm = wid >> 2, wn = wid & 3;

    wmma::fragment<wmma::accumulator, 16, 16, 8, float> acc[4][2];
#pragma unroll
    for (int i = 0; i < 4; i++)
#pragma unroll
        for (int j = 0; j < 2; j++) wmma::fill_fragment(acc[i][j], 0.0f);

    const float* Abase = A  + (size_t)tm * GT_M * K;
    const float* Bbase = Bm + (size_t)tn * GT_N * K;

    for (int k0 = 0; k0 < K; k0 += KCHUNK) {
        __syncthreads();
#pragma unroll
        for (int s = tid; s < GT_M * 4; s += 256) {
            int m = s >> 2, q = s & 3;
            *(float4*)&As[m * SPAD + q * 4] = *(const float4*)&Abase[(size_t)m * K + k0 + q * 4];
            *(float4*)&Bs[m * SPAD + q * 4] = *(const float4*)&Bbase[(size_t)m * K + k0 + q * 4];
        }
        __syncthreads();
#pragma unroll
        for (int ks = 0; ks < 2; ks++) {
            wmma::fragment<wmma::matrix_b, 16, 16, 8, wmma::precision::tf32, wmma::col_major> bf[2];
#pragma unroll
            for (int j = 0; j < 2; j++)
                wmma::load_matrix_sync(bf[j], &Bs[(wn * 32 + j * 16) * SPAD + ks * 8], SPAD);
#pragma unroll
            for (int i = 0; i < 4; i++) {
                wmma::fragment<wmma::matrix_a, 16, 16, 8, wmma::precision::tf32, wmma::row_major> af;
                wmma::load_matrix_sync(af, &As[(wm * 64 + i * 16) * SPAD + ks * 8], SPAD);
#pragma unroll
                for (int j = 0; j < 2; j++) wmma::mma_sync(acc[i][j], af, bf[j], acc[i][j]);
            }
        }
    }
#pragma unroll
    for (int i = 0; i < 4; i++)
#pragma unroll
        for (int j = 0; j < 2; j++) {
            int gm = tm * GT_M + wm * 64 + i * 16;
            int gn = tn * GT_N + wn * 32 + j * 16;
            wmma::store_matrix_sync(&g_xproj[(size_t)gm * GATES + gn], acc[i][j], GATES,
                                    wmma::mem_row_major);
        }
}

// ---------------- fused dual-layer persistent scan (fp16 operands, fp32 accum) ----------------
__global__ void __launch_bounds__(NT_SCAN) scan_fused()
{
    extern __shared__ char smem_raw[];

    const int tid  = threadIdx.x;
    const int w    = tid >> 5;
    const int lane = tid & 31;
    const int grp  = blockIdx.x >> 6;          // 0 = layer0, 1 = layer1
    const int c    = blockIdx.x & 63;          // gate-col block [32c, 32c+32)

    const __half hzero = __float2half(0.0f);
    // zero initial states
    for (int i = blockIdx.x * NT_SCAN + tid; i < BATCH * HID; i += NB_SCAN * NT_SCAN) {
        g_hbuf0[0][i] = hzero;
        g_hbuf1[0][i] = hzero;
    }

    // base round = own flag (only this CTA writes it; all flags equal between launches)
    unsigned round = ld_acquire_gpu(&g_flags[blockIdx.x][0]);

    if (grp == 0) {
        // ---------------- layer 0 ----------------
        __half* As = (__half*)smem_raw;             // [64][APADH]
        __half* Ws = As + 64 * APADH;               // [32][APADH]
        float*  sg = (float*)smem_raw;              // alias: [4][64][SGP]

        const int mh = w & 1;                       // m half (32 rows)
        const int kq = w >> 1;                      // k quarter (128 cols)

        {   // stage W slice once: 32 rows x 512 halfs (64 float4/row)
            const __half* Wg = g_Whh0h + (size_t)c * CCOLS * HID;
#pragma unroll 4
            for (int idx = tid; idx < CCOLS * 64; idx += NT_SCAN) {
                int n = idx >> 6, q = idx & 63;
                *(float4*)(Ws + n * APADH + q * 8) = *(const float4*)(Wg + (size_t)n * HID + q * 8);
            }
        }

        const int b0 = tid >> 3,  ul0 = tid & 7,  gc0 = ul0 * 4;
        const int p1 = tid + NT_SCAN;
        const int b1 = p1 >> 3,   ul1 = p1 & 7,   gc1 = ul1 * 4;
        const float4 bias0 = *(const float4*)(g_biasP[0] + c * CCOLS + gc0);
        const float4 bias1 = *(const float4*)(g_biasP[0] + c * CCOLS + gc1);
        const float* xpp0 = g_xproj + (size_t)b0 * SEQ * GATES + c * CCOLS + gc0;
        const float* xpp1 = g_xproj + (size_t)b1 * SEQ * GATES + c * CCOLS + gc1;
        const int u0 = c * 8 + ul0, u1 = c * 8 + ul1;
        float cst0 = 0.0f, cst1 = 0.0f;

        grid_barrier_round(++round);                // zero-init visible

        float4 xp0 = __ldcs((const float4*)xpp0);
        float4 xp1 = __ldcs((const float4*)xpp1);

        for (int r = 0; r < SEQ + 1; r++) {
            if (r < SEQ) {
                const int t = r;
                const __half* hread  = g_hbuf0[t & 1];
                __half*       hwrite = g_hbuf0[(t & 1) ^ 1];

                // warp-local stage: rows mh*32..+32, k-cols kq*128..+128 (16 f4/lane)
                {
                    const __half* src = hread + (size_t)(mh * 32) * HID + kq * 128;
                    __half* dst = As + (mh * 32) * APADH + kq * 128;
#pragma unroll
                    for (int i = 0; i < 16; i++) {
                        int idx = lane + 32 * i;
                        int row = idx >> 4, c8 = idx & 15;
                        *(float4*)(dst + row * APADH + c8 * 8) =
                            __ldcg((const float4*)(src + (size_t)row * HID + c8 * 8));
                    }
                }
                __syncwarp();

                wmma::fragment<wmma::accumulator, 16, 16, 16, float> acc[2][2];
#pragma unroll
                for (int i = 0; i < 2; i++)
#pragma unroll
                    for (int j = 0; j < 2; j++) wmma::fill_fragment(acc[i][j], 0.0f);

                const __half* Abase = As + (mh * 32) * APADH + kq * 128;
                const __half* Bbase = Ws + kq * 128;
#pragma unroll
                for (int ks = 0; ks < 8; ks++) {
                    wmma::fragment<wmma::matrix_a, 16, 16, 16, __half, wmma::row_major> af[2];
                    wmma::fragment<wmma::matrix_b, 16, 16, 16, __half, wmma::col_major> bf[2];
#pragma unroll
                    for (int i = 0; i < 2; i++)
                        wmma::load_matrix_sync(af[i], Abase + i * 16 * APADH + ks * 16, APADH);
#pragma unroll
                    for (int j = 0; j < 2; j++)
                        wmma::load_matrix_sync(bf[j], Bbase + j * 16 * APADH + ks * 16, APADH);
#pragma unroll
                    for (int i = 0; i < 2; i++)
#pragma unroll
                        for (int j = 0; j < 2; j++) wmma::mma_sync(acc[i][j], af[i], bf[j], acc[i][j]);
                }
                __syncthreads();
#pragma unroll
                for (int i = 0; i < 2; i++)
#pragma unroll
                    for (int j = 0; j < 2; j++)
                        wmma::store_matrix_sync(&sg[kq * (64 * SGP) + (mh * 32 + i * 16) * SGP + j * 16],
                                                acc[i][j], SGP, wmma::mem_row_major);
                __syncthreads();

                {
                    float4 s0 = *(const float4*)&sg[0 * (64 * SGP) + b0 * SGP + gc0];
                    float4 s1 = *(const float4*)&sg[1 * (64 * SGP) + b0 * SGP + gc0];
                    float4 s2 = *(const float4*)&sg[2 * (64 * SGP) + b0 * SGP + gc0];
                    float4 s3 = *(const float4*)&sg[3 * (64 * SGP) + b0 * SGP + gc0];
                    float pi = s0.x + s1.x + s2.x + s3.x + xp0.x + bias0.x;
                    float pf = s0.y + s1.y + s2.y + s3.y + xp0.y + bias0.y;
                    float pg = s0.z + s1.z + s2.z + s3.z + xp0.z + bias0.z;
                    float po = s0.w + s1.w + s2.w + s3.w + xp0.w + bias0.w;
                    float ig = sigm(pi), fg = sigm(pf), gg = tanhf(pg), og = sigm(po);
                    cst0 = fg * cst0 + ig * gg;
                    hwrite[b0 * HID + u0] = __float2half(og * tanhf(cst0));
                }
                {
                    float4 s0 = *(const float4*)&sg[0 * (64 * SGP) + b1 * SGP + gc1];
                    float4 s1 = *(const float4*)&sg[1 * (64 * SGP) + b1 * SGP + gc1];
                    float4 s2 = *(const float4*)&sg[2 * (64 * SGP) + b1 * SGP + gc1];
                    float4 s3 = *(const float4*)&sg[3 * (64 * SGP) + b1 * SGP + gc1];
                    float pi = s0.x + s1.x + s2.x + s3.x + xp1.x + bias1.x;
                    float pf = s0.y + s1.y + s2.y + s3.y + xp1.y + bias1.y;
                    float pg = s0.z + s1.z + s2.z + s3.z + xp1.z + bias1.z;
                    float po = s0.w + s1.w + s2.w + s3.w + xp1.w + bias1.w;
                    float ig = sigm(pi), fg = sigm(pf), gg = tanhf(pg), og = sigm(po);
                    cst1 = fg * cst1 + ig * gg;
                    hwrite[b1 * HID + u1] = __float2half(og * tanhf(cst1));
                }
                // prefetch next xproj before the barrier
                int tn2 = (t + 1 < SEQ) ? (t + 1) : (SEQ - 1);
                xp0 = __ldcs((const float4*)(xpp0 + (size_t)tn2 * GATES));
                xp1 = __ldcs((const float4*)(xpp1 + (size_t)tn2 * GATES));
            }
            grid_barrier_round(++round);
        }
    } else {
        // ---------------- layer 1 (lag 1) ----------------
        __half* Ws1 = (__half*)smem_raw;            // [32][W1PADH]: cols 0-511 Wih1, 512-1023 Whh1
        __half* As1 = Ws1 + 32 * W1PADH;            // [32][APADH]
        float*  sg  = (float*)As1;                  // alias: [4][32][SGP]

        const int mhw = w & 1;                      // 16-row half of the 32-row m-half
        const int kq  = w >> 1;                     // 128-col k quarter

        {   // stage concat W once: 32 rows x 1024 halfs (128 f4/row)
            const __half* Wx = g_Wih1h + (size_t)c * CCOLS * HID;
            const __half* Wh = g_Whh1h + (size_t)c * CCOLS * HID;
#pragma unroll 4
            for (int idx = tid; idx < CCOLS * 128; idx += NT_SCAN) {
                int n = idx >> 7, q = idx & 127;
                const __half* src = (q < 64) ? (Wx + (size_t)n * HID + q * 8)
                                             : (Wh + (size_t)n * HID + (q - 64) * 8);
                *(float4*)(Ws1 + n * W1PADH + q * 8) = *(const float4*)src;
            }
        }

        const int bl = tid >> 3, ul = tid & 7, gc = ul * 4;
        const float4 biasq = *(const float4*)(g_biasP[1] + c * CCOLS + gc);
        const int u = c * 8 + ul;
        float cstA = 0.0f, cstB = 0.0f;

        grid_barrier_round(++round);

        for (int r = 0; r < SEQ + 1; r++) {
            if (r >= 1) {
                const int t = r - 1;
                const __half* h0read = g_hbuf0[(t & 1) ^ 1];   // h0[t]
                const __half* h1read = g_hbuf1[t & 1];         // h1[t-1]
                __half*       hwrite = g_hbuf1[(t & 1) ^ 1];

#pragma unroll
                for (int mh2 = 0; mh2 < 2; mh2++) {
                    const int rb = mh2 * 32;

                    wmma::fragment<wmma::accumulator, 16, 16, 16, float> acc[2];
                    wmma::fill_fragment(acc[0], 0.0f);
                    wmma::fill_fragment(acc[1], 0.0f);

#pragma unroll
                    for (int pass = 0; pass < 2; pass++) {
                        const __half* src = pass ? h1read : h0read;
                        {   // warp-private stage: rows rb+mhw*16..+16, cols kq*128..+128 (8 f4/lane)
                            const __half* s = src + (size_t)(rb + mhw * 16) * HID + kq * 128;
                            __half* dst = As1 + (mhw * 16) * APADH + kq * 128;
#pragma unroll
                            for (int i = 0; i < 8; i++) {
                                int idx = lane + 32 * i;
                                int row = idx >> 4, c8 = idx & 15;
                                *(float4*)(dst + row * APADH + c8 * 8) =
                                    __ldcg((const float4*)(s + (size_t)row * HID + c8 * 8));
                            }
                        }
                        __syncwarp();

                        const __half* Abase = As1 + (mhw * 16) * APADH + kq * 128;
                        const __half* Bbase = Ws1 + pass * 512 + kq * 128;
#pragma unroll
                        for (int ks = 0; ks < 8; ks++) {
                            wmma::fragment<wmma::matrix_a, 16, 16, 16, __half, wmma::row_major> af;
                            wmma::fragment<wmma::matrix_b, 16, 16, 16, __half, wmma::col_major> bf[2];
                            wmma::load_matrix_sync(af, Abase + ks * 16, APADH);
#pragma unroll
                            for (int j = 0; j < 2; j++)
                                wmma::load_matrix_sync(bf[j], Bbase + j * 16 * W1PADH + ks * 16, W1PADH);
#pragma unroll
                            for (int j = 0; j < 2; j++) wmma::mma_sync(acc[j], af, bf[j], acc[j]);
                        }
                        __syncwarp();
                    }
                    __syncthreads();   // all warps done with As1 before sg alias write
#pragma unroll
                    for (int j = 0; j < 2; j++)
                        wmma::store_matrix_sync(&sg[kq * (32 * SGP) + (mhw * 16) * SGP + j * 16],
                                                acc[j], SGP, wmma::mem_row_major);
                    __syncthreads();

                    {   // elementwise for 32 batches
                        float4 s0 = *(const float4*)&sg[0 * (32 * SGP) + bl * SGP + gc];
                        float4 s1 = *(const float4*)&sg[1 * (32 * SGP) + bl * SGP + gc];
                        float4 s2 = *(const float4*)&sg[2 * (32 * SGP) + bl * SGP + gc];
                        float4 s3 = *(const float4*)&sg[3 * (32 * SGP) + bl * SGP + gc];
                        float pi = s0.x + s1.x + s2.x + s3.x + biasq.x;
                        float pf = s0.y + s1.y + s2.y + s3.y + biasq.y;
                        float pg = s0.z + s1.z + s2.z + s3.z + biasq.z;
                        float po = s0.w + s1.w + s2.w + s3.w + biasq.w;
                        float ig = sigm(pi), fg = sigm(pf), gg = tanhf(pg), og = sigm(po);
                        float& cst = mh2 ? cstB : cstA;
                        cst = fg * cst + ig * gg;
                        hwrite[(rb + bl) * HID + u] = __float2half(og * tanhf(cst));
                    }
                    __syncthreads();   // elementwise done before next m-half restages As1/sg
                }
            }
            grid_barrier_round(++round);
        }
    }
}

// ---------------- output projection (split-K x4, half h) ----------------
__global__ void out_kernel(const float* __restrict__ Wout, const float* __restrict__ bout,
                           float* __restrict__ out)
{
    __shared__ float red[512];
    int b = blockIdx.x;
    int t = threadIdx.x;          // 512
    int o = t & 127, q = t >> 7;
    const __half2* h2 = (const __half2*)(g_hbuf1[0] + b * HID) + q * 64;   // final h1 in buffer 0
    const float2*  w2 = (const float2*)(Wout + (size_t)o * HID) + q * 64;
    float acc = 0.0f;
#pragma unroll
    for (int i = 0; i < 64; i++) {
        float2 hh = __half22float2(h2[i]);
        float2 ww = w2[i];
        acc += hh.x * ww.x + hh.y * ww.y;
    }
    red[t] = acc;
    __syncthreads();
    if (t < 128)
        out[b * ODIM + t] = red[t] + red[t + 128] + red[t + 256] + red[t + 384] + bout[t];
}

// ---------------- launch ----------------
extern "C" void kernel_launch(void* const* d_in, const int* in_sizes, int n_in,
                              void* d_out, int out_size)
{
    (void)in_sizes; (void)n_in; (void)out_size;
    const float* prim = (const float*)d_in[0];
    const float* aux  = (const float*)d_in[1];
    const float* Wih0 = (const float*)d_in[2];
    const float* Whh0 = (const float*)d_in[3];
    const float* bih0 = (const float*)d_in[4];
    const float* bhh0 = (const float*)d_in[5];
    const float* Wih1 = (const float*)d_in[6];
    const float* Whh1 = (const float*)d_in[7];
    const float* bih1 = (const float*)d_in[8];
    const float* bhh1 = (const float*)d_in[9];
    const float* Wout = (const float*)d_in[10];
    const float* bout = (const float*)d_in[11];
    float* out = (float*)d_out;

    static bool attr_set = false;
    if (!attr_set) {
        cudaFuncSetAttribute(scan_fused, cudaFuncAttributeMaxDynamicSharedMemorySize,
                             SCAN_SMEM_BYTES);
        attr_set = true;
    }

    prep_kernel<<<1024, 256>>>(prim, aux, Wih0, Whh0, bih0, bhh0, Wih1, Whh1, bih1, bhh1);
    gemm_tf32<<<dim3(16, 256), 256>>>();                      // x_proj0
    scan_fused<<<NB_SCAN, NT_SCAN, SCAN_SMEM_BYTES>>>();      // both layers, pipelined
    out_kernel<<<BATCH, 512>>>(Wout, bout, out);
}

// round 12
// speedup vs baseline: 3.1499x; 1.1085x over previous
#include <cuda_runtime.h>
#include <cuda_bf16.h>
#include <cuda_fp16.h>
#include <mma.h>

using namespace nvcuda;

#define BATCH 64
#define SEQ   512
#define HID   512
#define GATES 2048
#define KIN   96
#define ODIM  128

#define NB_SCAN 128     // 64 layer-0 CTAs + 64 layer-1 CTAs
#define NT_SCAN 256
#define CCOLS   32
#define APADH   520     // 512+8 halfs: row stride 1040B ≡ 16B mod 128B
#define W1PADH  1032    // 1024+8 halfs: 2064B ≡ 16B mod 128B
#define SGP     36
// layer-0: As half[64][APADH] + Ws half[32][APADH]; sg(float) aliases As
#define L0_TOTAL_B   ((64 + 32) * APADH * 2)           // 99,840
// layer-1: Ws1 half[32][W1PADH] + As1 half[64][W1PADH]; sg(float) aliases As1
#define L1_TOTAL_B   ((32 + 64) * W1PADH * 2)          // 198,144
#define SCAN_SMEM_BYTES L1_TOTAL_B                     // 198,144 B (< 227 KB)

// ---------------- static device scratch ----------------
__device__ float  g_xproj[(size_t)BATCH * SEQ * GATES];
__device__ float  g_xcat[(size_t)BATCH * SEQ * KIN];
__device__ float  g_Wih0p[GATES * KIN];
__device__ __half g_Whh0h[GATES * HID];
__device__ __half g_Wih1h[GATES * HID];
__device__ __half g_Whh1h[GATES * HID];
__device__ float  g_biasP[2][GATES];
__device__ __half g_hbuf0[2][BATCH * HID];
__device__ __half g_hbuf1[2][BATCH * HID];
__device__ unsigned g_flags[NB_SCAN][32];   // per-CTA round flags, 128B apart

// ---------------- sync primitives ----------------
__device__ __forceinline__ unsigned ld_acquire_gpu(const unsigned* p) {
    unsigned v;
    asm volatile("ld.acquire.gpu.global.u32 %0, [%1];" : "=r"(v) : "l"(p) : "memory");
    return v;
}
__device__ __forceinline__ void st_release_gpu(unsigned* p, unsigned v) {
    asm volatile("st.release.gpu.global.u32 [%0], %1;" :: "l"(p), "r"(v) : "memory");
}

// all-to-all flag barrier: arrival = 1 release store to own flag; wait = warp 0
// polls all 128 flags in parallel. Monotonic rounds, replay-safe.
__device__ __forceinline__ void grid_barrier_round(unsigned round) {
    __syncthreads();
    if (threadIdx.x < 32) {
        if (threadIdx.x == 0)
            st_release_gpu(&g_flags[blockIdx.x][0], round);
        const int lane = threadIdx.x;
        bool ok;
        do {
            ok = true;
#pragma unroll
            for (int i = 0; i < NB_SCAN / 32; i++) {
                unsigned f = ld_acquire_gpu(&g_flags[lane + 32 * i][0]);
                ok &= ((int)(f - round) >= 0);
            }
        } while (!__all_sync(0xffffffffu, ok));
    }
    __syncthreads();
}

__device__ __forceinline__ float sigm(float x) { return 1.0f / (1.0f + expf(-x)); }

__device__ __forceinline__ float tf32_rna(float x) {
    unsigned u;
    asm("cvt.rna.tf32.f32 %0, %1;" : "=r"(u) : "f"(x));
    return __uint_as_float(u);
}

// ---------------- prep ----------------
__global__ void prep_kernel(const float* __restrict__ prim, const float* __restrict__ aux,
                            const float* __restrict__ Wih0, const float* __restrict__ Whh0,
                            const float* __restrict__ bih0, const float* __restrict__ bhh0,
                            const float* __restrict__ Wih1, const float* __restrict__ Whh1,
                            const float* __restrict__ bih1, const float* __restrict__ bhh1)
{
    size_t tid = (size_t)blockIdx.x * blockDim.x + threadIdx.x;
    size_t nth = (size_t)gridDim.x * blockDim.x;

    for (size_t i = tid; i < (size_t)BATCH * SEQ * KIN; i += nth) {
        int k = (int)(i % KIN);
        size_t bt = i / KIN;
        int b = (int)(bt / SEQ);
        g_xcat[i] = tf32_rna((k < 64) ? prim[bt * 64 + k] : aux[b * 32 + (k - 64)]);
    }
    for (size_t i = tid; i < (size_t)GATES * HID; i += nth) {
        int k  = (int)(i % HID);
        int cp = (int)(i / HID);
        int u = cp >> 2, gi = cp & 3;
        size_t r = (size_t)(gi * HID + u) * HID + k;
        g_Whh0h[i] = __float2half(Whh0[r]);
        g_Whh1h[i] = __float2half(Whh1[r]);
        g_Wih1h[i] = __float2half(Wih1[r]);
    }
    for (size_t i = tid; i < (size_t)GATES * KIN; i += nth) {
        int k  = (int)(i % KIN);
        int cp = (int)(i / KIN);
        int u = cp >> 2, gi = cp & 3;
        g_Wih0p[i] = tf32_rna(Wih0[(size_t)(gi * HID + u) * KIN + k]);
    }
    for (size_t i = tid; i < GATES; i += nth) {
        int u = (int)(i >> 2), gi = (int)(i & 3);
        int r = gi * HID + u;
        g_biasP[0][i] = bih0[r] + bhh0[r];
        g_biasP[1][i] = bih1[r] + bhh1[r];
    }
}

// ---------------- x_proj0 GEMM (tf32 wmma) ----------------
#define GT_M 128
#define GT_N 128
#define KCHUNK 16
#define SPAD 20

__global__ void __launch_bounds__(256) gemm_tf32()
{
    __shared__ float As[GT_M * SPAD];
    __shared__ float Bs[GT_N * SPAD];

    const float* A  = g_xcat;
    const float* Bm = g_Wih0p;
    const int K     = KIN;

    int tn = blockIdx.x;
    int tm = blockIdx.y;
    int tid = threadIdx.x;
    int wid = tid >> 5;
    int wm = wid >> 2, wn = wid & 3;

    wmma::fragment<wmma::accumulator, 16, 16, 8, float> acc[4][2];
#pragma unroll
    for (int i = 0; i < 4; i++)
#pragma unroll
        for (int j = 0; j < 2; j++) wmma::fill_fragment(acc[i][j], 0.0f);

    const float* Abase = A  + (size_t)tm * GT_M * K;
    const float* Bbase = Bm + (size_t)tn * GT_N * K;

    for (int k0 = 0; k0 < K; k0 += KCHUNK) {
        __syncthreads();
#pragma unroll
        for (int s = tid; s < GT_M * 4; s += 256) {
            int m = s >> 2, q = s & 3;
            *(float4*)&As[m * SPAD + q * 4] = *(const float4*)&Abase[(size_t)m * K + k0 + q * 4];
            *(float4*)&Bs[m * SPAD + q * 4] = *(const float4*)&Bbase[(size_t)m * K + k0 + q * 4];
        }
        __syncthreads();
#pragma unroll
        for (int ks = 0; ks < 2; ks++) {
            wmma::fragment<wmma::matrix_b, 16, 16, 8, wmma::precision::tf32, wmma::col_major> bf[2];
#pragma unroll
            for (int j = 0; j < 2; j++)
                wmma::load_matrix_sync(bf[j], &Bs[(wn * 32 + j * 16) * SPAD + ks * 8], SPAD);
#pragma unroll
            for (int i = 0; i < 4; i++) {
                wmma::fragment<wmma::matrix_a, 16, 16, 8, wmma::precision::tf32, wmma::row_major> af;
                wmma::load_matrix_sync(af, &As[(wm * 64 + i * 16) * SPAD + ks * 8], SPAD);
#pragma unroll
                for (int j = 0; j < 2; j++) wmma::mma_sync(acc[i][j], af, bf[j], acc[i][j]);
            }
        }
    }
#pragma unroll
    for (int i = 0; i < 4; i++)
#pragma unroll
        for (int j = 0; j < 2; j++) {
            int gm = tm * GT_M + wm * 64 + i * 16;
            int gn = tn * GT_N + wn * 32 + j * 16;
            wmma::store_matrix_sync(&g_xproj[(size_t)gm * GATES + gn], acc[i][j], GATES,
                                    wmma::mem_row_major);
        }
}

// ---------------- fused dual-layer persistent scan (fp16 operands, fp32 accum) ----------------
__global__ void __launch_bounds__(NT_SCAN) scan_fused()
{
    extern __shared__ char smem_raw[];

    const int tid  = threadIdx.x;
    const int w    = tid >> 5;
    const int lane = tid & 31;
    const int grp  = blockIdx.x >> 6;          // 0 = layer0, 1 = layer1
    const int c    = blockIdx.x & 63;          // gate-col block [32c, 32c+32)

    const __half hzero = __float2half(0.0f);
    for (int i = blockIdx.x * NT_SCAN + tid; i < BATCH * HID; i += NB_SCAN * NT_SCAN) {
        g_hbuf0[0][i] = hzero;
        g_hbuf1[0][i] = hzero;
    }

    unsigned round = ld_acquire_gpu(&g_flags[blockIdx.x][0]);

    if (grp == 0) {
        // ---------------- layer 0 ----------------
        __half* As = (__half*)smem_raw;             // [64][APADH]
        __half* Ws = As + 64 * APADH;               // [32][APADH]
        float*  sg = (float*)smem_raw;              // alias: [4][64][SGP]

        const int mh = w & 1;                       // m half (32 rows)
        const int kq = w >> 1;                      // k quarter (128 cols)

        {   // stage W slice once
            const __half* Wg = g_Whh0h + (size_t)c * CCOLS * HID;
#pragma unroll 4
            for (int idx = tid; idx < CCOLS * 64; idx += NT_SCAN) {
                int n = idx >> 6, q = idx & 63;
                *(float4*)(Ws + n * APADH + q * 8) = *(const float4*)(Wg + (size_t)n * HID + q * 8);
            }
        }

        const int b0 = tid >> 3,  ul0 = tid & 7,  gc0 = ul0 * 4;
        const int p1 = tid + NT_SCAN;
        const int b1 = p1 >> 3,   ul1 = p1 & 7,   gc1 = ul1 * 4;
        const float4 bias0 = *(const float4*)(g_biasP[0] + c * CCOLS + gc0);
        const float4 bias1 = *(const float4*)(g_biasP[0] + c * CCOLS + gc1);
        const float* xpp0 = g_xproj + (size_t)b0 * SEQ * GATES + c * CCOLS + gc0;
        const float* xpp1 = g_xproj + (size_t)b1 * SEQ * GATES + c * CCOLS + gc1;
        const int u0 = c * 8 + ul0, u1 = c * 8 + ul1;
        float cst0 = 0.0f, cst1 = 0.0f;

        grid_barrier_round(++round);

        float4 xp0 = __ldcs((const float4*)xpp0);
        float4 xp1 = __ldcs((const float4*)xpp1);

        for (int r = 0; r < SEQ + 1; r++) {
            if (r < SEQ) {
                const int t = r;
                const __half* hread  = g_hbuf0[t & 1];
                __half*       hwrite = g_hbuf0[(t & 1) ^ 1];

                {   // warp-local stage: rows mh*32..+32, cols kq*128..+128 (16 f4/lane)
                    const __half* src = hread + (size_t)(mh * 32) * HID + kq * 128;
                    __half* dst = As + (mh * 32) * APADH + kq * 128;
#pragma unroll
                    for (int i = 0; i < 16; i++) {
                        int idx = lane + 32 * i;
                        int row = idx >> 4, c8 = idx & 15;
                        *(float4*)(dst + row * APADH + c8 * 8) =
                            __ldcg((const float4*)(src + (size_t)row * HID + c8 * 8));
                    }
                }
                __syncwarp();

                wmma::fragment<wmma::accumulator, 16, 16, 16, float> acc[2][2];
#pragma unroll
                for (int i = 0; i < 2; i++)
#pragma unroll
                    for (int j = 0; j < 2; j++) wmma::fill_fragment(acc[i][j], 0.0f);

                const __half* Abase = As + (mh * 32) * APADH + kq * 128;
                const __half* Bbase = Ws + kq * 128;
#pragma unroll
                for (int ks = 0; ks < 8; ks++) {
                    wmma::fragment<wmma::matrix_a, 16, 16, 16, __half, wmma::row_major> af[2];
                    wmma::fragment<wmma::matrix_b, 16, 16, 16, __half, wmma::col_major> bf[2];
#pragma unroll
                    for (int i = 0; i < 2; i++)
                        wmma::load_matrix_sync(af[i], Abase + i * 16 * APADH + ks * 16, APADH);
#pragma unroll
                    for (int j = 0; j < 2; j++)
                        wmma::load_matrix_sync(bf[j], Bbase + j * 16 * APADH + ks * 16, APADH);
#pragma unroll
                    for (int i = 0; i < 2; i++)
#pragma unroll
                        for (int j = 0; j < 2; j++) wmma::mma_sync(acc[i][j], af[i], bf[j], acc[i][j]);
                }
                __syncthreads();
#pragma unroll
                for (int i = 0; i < 2; i++)
#pragma unroll
                    for (int j = 0; j < 2; j++)
                        wmma::store_matrix_sync(&sg[kq * (64 * SGP) + (mh * 32 + i * 16) * SGP + j * 16],
                                                acc[i][j], SGP, wmma::mem_row_major);
                __syncthreads();

                {
                    float4 s0 = *(const float4*)&sg[0 * (64 * SGP) + b0 * SGP + gc0];
                    float4 s1 = *(const float4*)&sg[1 * (64 * SGP) + b0 * SGP + gc0];
                    float4 s2 = *(const float4*)&sg[2 * (64 * SGP) + b0 * SGP + gc0];
                    float4 s3 = *(const float4*)&sg[3 * (64 * SGP) + b0 * SGP + gc0];
                    float pi = s0.x + s1.x + s2.x + s3.x + xp0.x + bias0.x;
                    float pf = s0.y + s1.y + s2.y + s3.y + xp0.y + bias0.y;
                    float pg = s0.z + s1.z + s2.z + s3.z + xp0.z + bias0.z;
                    float po = s0.w + s1.w + s2.w + s3.w + xp0.w + bias0.w;
                    float ig = sigm(pi), fg = sigm(pf), gg = tanhf(pg), og = sigm(po);
                    cst0 = fg * cst0 + ig * gg;
                    hwrite[b0 * HID + u0] = __float2half(og * tanhf(cst0));
                }
                {
                    float4 s0 = *(const float4*)&sg[0 * (64 * SGP) + b1 * SGP + gc1];
                    float4 s1 = *(const float4*)&sg[1 * (64 * SGP) + b1 * SGP + gc1];
                    float4 s2 = *(const float4*)&sg[2 * (64 * SGP) + b1 * SGP + gc1];
                    float4 s3 = *(const float4*)&sg[3 * (64 * SGP) + b1 * SGP + gc1];
                    float pi = s0.x + s1.x + s2.x + s3.x + xp1.x + bias1.x;
                    float pf = s0.y + s1.y + s2.y + s3.y + xp1.y + bias1.y;
                    float pg = s0.z + s1.z + s2.z + s3.z + xp1.z + bias1.z;
                    float po = s0.w + s1.w + s2.w + s3.w + xp1.w + bias1.w;
                    float ig = sigm(pi), fg = sigm(pf), gg = tanhf(pg), og = sigm(po);
                    cst1 = fg * cst1 + ig * gg;
                    hwrite[b1 * HID + u1] = __float2half(og * tanhf(cst1));
                }
                int tn2 = (t + 1 < SEQ) ? (t + 1) : (SEQ - 1);
                xp0 = __ldcs((const float4*)(xpp0 + (size_t)tn2 * GATES));
                xp1 = __ldcs((const float4*)(xpp1 + (size_t)tn2 * GATES));
            }
            grid_barrier_round(++round);
        }
    } else {
        // ---------------- layer 1 (lag 1, single-segment: full 64-row concat A) ----------------
        __half* Ws1 = (__half*)smem_raw;            // [32][W1PADH]: cols 0-511 Wih1, 512-1023 Whh1
        __half* As1 = Ws1 + 32 * W1PADH;            // [64][W1PADH]: concat [h0(t) | h1(t-1)]
        float*  sg  = (float*)As1;                  // alias: [4][64][SGP]

        const int mh = w & 1;                       // m half (32 rows)
        const int kq = w >> 1;                      // 256-col quarter of concat K=1024

        {   // stage concat W once: 32 rows x 1024 halfs
            const __half* Wx = g_Wih1h + (size_t)c * CCOLS * HID;
            const __half* Wh = g_Whh1h + (size_t)c * CCOLS * HID;
#pragma unroll 4
            for (int idx = tid; idx < CCOLS * 128; idx += NT_SCAN) {
                int n = idx >> 7, q = idx & 127;
                const __half* src = (q < 64) ? (Wx + (size_t)n * HID + q * 8)
                                             : (Wh + (size_t)n * HID + (q - 64) * 8);
                *(float4*)(Ws1 + n * W1PADH + q * 8) = *(const float4*)src;
            }
        }

        const int b0 = tid >> 3,  ul0 = tid & 7,  gc0 = ul0 * 4;
        const int p1 = tid + NT_SCAN;
        const int b1 = p1 >> 3,   ul1 = p1 & 7,   gc1 = ul1 * 4;
        const float4 bias0 = *(const float4*)(g_biasP[1] + c * CCOLS + gc0);
        const float4 bias1 = *(const float4*)(g_biasP[1] + c * CCOLS + gc1);
        const int u0 = c * 8 + ul0, u1 = c * 8 + ul1;
        float cst0 = 0.0f, cst1 = 0.0f;

        grid_barrier_round(++round);

        for (int r = 0; r < SEQ + 1; r++) {
            if (r >= 1) {
                const int t = r - 1;
                const __half* h0read = g_hbuf0[(t & 1) ^ 1];   // h0[t]
                const __half* h1read = g_hbuf1[t & 1];         // h1[t-1]
                __half*       hwrite = g_hbuf1[(t & 1) ^ 1];

                {   // warp-local stage: rows mh*32..+32, concat cols kq*256..+256 (32 f4/lane)
                    const __half* src = (kq < 2) ? h0read : h1read;
                    const int kc = (kq & 1) * 256;             // col offset within source
                    const __half* s = src + (size_t)(mh * 32) * HID + kc;
                    __half* dst = As1 + (mh * 32) * W1PADH + kq * 256;
#pragma unroll
                    for (int i = 0; i < 32; i++) {
                        int idx = lane + 32 * i;
                        int row = idx >> 5, c8 = idx & 31;
                        *(float4*)(dst + row * W1PADH + c8 * 8) =
                            __ldcg((const float4*)(s + (size_t)row * HID + c8 * 8));
                    }
                }
                __syncwarp();

                wmma::fragment<wmma::accumulator, 16, 16, 16, float> acc[2][2];
#pragma unroll
                for (int i = 0; i < 2; i++)
#pragma unroll
                    for (int j = 0; j < 2; j++) wmma::fill_fragment(acc[i][j], 0.0f);

                const __half* Abase = As1 + (mh * 32) * W1PADH + kq * 256;
                const __half* Bbase = Ws1 + kq * 256;
#pragma unroll
                for (int ks = 0; ks < 16; ks++) {
                    wmma::fragment<wmma::matrix_a, 16, 16, 16, __half, wmma::row_major> af[2];
                    wmma::fragment<wmma::matrix_b, 16, 16, 16, __half, wmma::col_major> bf[2];
#pragma unroll
                    for (int i = 0; i < 2; i++)
                        wmma::load_matrix_sync(af[i], Abase + i * 16 * W1PADH + ks * 16, W1PADH);
#pragma unroll
                    for (int j = 0; j < 2; j++)
                        wmma::load_matrix_sync(bf[j], Bbase + j * 16 * W1PADH + ks * 16, W1PADH);
#pragma unroll
                    for (int i = 0; i < 2; i++)
#pragma unroll
                        for (int j = 0; j < 2; j++) wmma::mma_sync(acc[i][j], af[i], bf[j], acc[i][j]);
                }
                __syncthreads();   // all warps done reading As1 before sg (alias) write
#pragma unroll
                for (int i = 0; i < 2; i++)
#pragma unroll
                    for (int j = 0; j < 2; j++)
                        wmma::store_matrix_sync(&sg[kq * (64 * SGP) + (mh * 32 + i * 16) * SGP + j * 16],
                                                acc[i][j], SGP, wmma::mem_row_major);
                __syncthreads();

                {
                    float4 s0 = *(const float4*)&sg[0 * (64 * SGP) + b0 * SGP + gc0];
                    float4 s1 = *(const float4*)&sg[1 * (64 * SGP) + b0 * SGP + gc0];
                    float4 s2 = *(const float4*)&sg[2 * (64 * SGP) + b0 * SGP + gc0];
                    float4 s3 = *(const float4*)&sg[3 * (64 * SGP) + b0 * SGP + gc0];
                    float pi = s0.x + s1.x + s2.x + s3.x + bias0.x;
                    float pf = s0.y + s1.y + s2.y + s3.y + bias0.y;
                    float pg = s0.z + s1.z + s2.z + s3.z + bias0.z;
                    float po = s0.w + s1.w + s2.w + s3.w + bias0.w;
                    float ig = sigm(pi), fg = sigm(pf), gg = tanhf(pg), og = sigm(po);
                    cst0 = fg * cst0 + ig * gg;
                    hwrite[b0 * HID + u0] = __float2half(og * tanhf(cst0));
                }
                {
                    float4 s0 = *(const float4*)&sg[0 * (64 * SGP) + b1 * SGP + gc1];
                    float4 s1 = *(const float4*)&sg[1 * (64 * SGP) + b1 * SGP + gc1];
                    float4 s2 = *(const float4*)&sg[2 * (64 * SGP) + b1 * SGP + gc1];
                    float4 s3 = *(const float4*)&sg[3 * (64 * SGP) + b1 * SGP + gc1];
                    float pi = s0.x + s1.x + s2.x + s3.x + bias1.x;
                    float pf = s0.y + s1.y + s2.y + s3.y + bias1.y;
                    float pg = s0.z + s1.z + s2.z + s3.z + bias1.z;
                    float po = s0.w + s1.w + s2.w + s3.w + bias1.w;
                    float ig = sigm(pi), fg = sigm(pf), gg = tanhf(pg), og = sigm(po);
                    cst1 = fg * cst1 + ig * gg;
                    hwrite[b1 * HID + u1] = __float2half(og * tanhf(cst1));
                }
            }
            grid_barrier_round(++round);
        }
    }
}

// ---------------- output projection (split-K x2 + smem reduce, half h) ----------------
__global__ void out_kernel(const float* __restrict__ Wout, const float* __restrict__ bout,
                           float* __restrict__ out)
{
    __shared__ float red[256];
    int b = blockIdx.x;
    int t = threadIdx.x;          // 256
    int o = t & 127, half = t >> 7;
    const __half2* h2 = (const __half2*)(g_hbuf1[0] + b * HID) + half * 128;
    const float2*  w2 = (const float2*)(Wout + (size_t)o * HID) + half * 128;
    float acc = 0.0f;
#pragma unroll 16
    for (int i = 0; i < 128; i++) {
        float2 hh = __half22float2(h2[i]);
        float2 ww = w2[i];
        acc += hh.x * ww.x + hh.y * ww.y;
    }
    red[t] = acc;
    __syncthreads();
    if (t < 128) out[b * ODIM + t] = red[t] + red[t + 128] + bout[t];
}

// ---------------- launch ----------------
extern "C" void kernel_launch(void* const* d_in, const int* in_sizes, int n_in,
                              void* d_out, int out_size)
{
    (void)in_sizes; (void)n_in; (void)out_size;
    const float* prim = (const float*)d_in[0];
    const float* aux  = (const float*)d_in[1];
    const float* Wih0 = (const float*)d_in[2];
    const float* Whh0 = (const float*)d_in[3];
    const float* bih0 = (const float*)d_in[4];
    const float* bhh0 = (const float*)d_in[5];
    const float* Wih1 = (const float*)d_in[6];
    const float* Whh1 = (const float*)d_in[7];
    const float* bih1 = (const float*)d_in[8];
    const float* bhh1 = (const float*)d_in[9];
    const float* Wout = (const float*)d_in[10];
    const float* bout = (const float*)d_in[11];
    float* out = (float*)d_out;

    static bool attr_set = false;
    if (!attr_set) {
        cudaFuncSetAttribute(scan_fused, cudaFuncAttributeMaxDynamicSharedMemorySize,
                             SCAN_SMEM_BYTES);
        attr_set = true;
    }

    prep_kernel<<<1024, 256>>>(prim, aux, Wih0, Whh0, bih0, bhh0, Wih1, Whh1, bih1, bhh1);
    gemm_tf32<<<dim3(16, 256), 256>>>();                      // x_proj0
    scan_fused<<<NB_SCAN, NT_SCAN, SCAN_SMEM_BYTES>>>();      // both layers, pipelined
    out_kernel<<<BATCH, 256>>>(Wout, bout, out);
}